// round 15
// baseline (speedup 1.0000x reference)
#include <cuda_runtime.h>
#include <cuda_fp16.h>
#include <cstdint>

#define Bz 32
#define Vz 21
#define Dz 512
#define Pz 64
#define INz 32768
#define OUTz 96
#define Ez 8
#define Rz 8
#define Hz 256
#define NROWS (Bz*Vz)          /* 672 */
#define NCOLS (OUTz + Ez*Rz)   /* 160 */
#define SPLITK 64
#define KC (INz/SPLITK)        /* 512 */
#define SCALE 2.0f

// GEMM tiling
#define MT 64
#define KT 32
#define NSTEP (KC/KT)          /* 16 */
#define AH_OFF 0
#define BH_OFF 5120            /* 64*80 */
#define STAGE  17920           /* 5120 + 160*80 */
#define SM_TOTAL (2*STAGE)     /* 35840 */

// ---------------- device scratch ----------------
__device__ float g_pooled[Bz*Dz];
__device__ float g_h[Bz*Hz];
__device__ float g_acc[NROWS*NCOLS];
__device__ __half g_Bf[(size_t)NCOLS*INz];   // B-matrix, single fp16 plane

// ---------------- PTX helpers ----------------
__device__ __forceinline__ uint32_t smem_u32(const void* p) {
    uint32_t a;
    asm("{ .reg .u64 t; cvta.to.shared.u64 t, %1; cvt.u32.u64 %0, t; }" : "=r"(a) : "l"(p));
    return a;
}
#define CP8(dst, src)   asm volatile("cp.async.ca.shared.global [%0], [%1], 8;" :: "r"(dst), "l"(src) : "memory")
#define CP_COMMIT()     asm volatile("cp.async.commit_group;" ::: "memory")
#define CP_WAIT0()      asm volatile("cp.async.wait_group 0;" ::: "memory")
#define LDSM4(r0,r1,r2,r3,addr) \
    asm volatile("ldmatrix.sync.aligned.m8n8.x4.shared.b16 {%0,%1,%2,%3}, [%4];" \
        : "=r"(r0),"=r"(r1),"=r"(r2),"=r"(r3) : "r"(addr))
#define LDSM2(r0,r1,addr) \
    asm volatile("ldmatrix.sync.aligned.m8n8.x2.shared.b16 {%0,%1}, [%2];" \
        : "=r"(r0),"=r"(r1) : "r"(addr))
#define MMAH(d, a, b0, b1) \
    asm volatile("mma.sync.aligned.m16n8k16.row.col.f32.f16.f16.f32 " \
        "{%0,%1,%2,%3},{%4,%5,%6,%7},{%8,%9},{%0,%1,%2,%3};" \
        : "+f"((d)[0]),"+f"((d)[1]),"+f"((d)[2]),"+f"((d)[3]) \
        : "r"((a)[0]),"r"((a)[1]),"r"((a)[2]),"r"((a)[3]), "r"(b0),"r"(b1))

__device__ __forceinline__ void cvt16(float4 f, uint2& h) {
    __half2 h01 = __floats2half2_rn(f.x, f.y);
    __half2 h23 = __floats2half2_rn(f.z, f.w);
    h.x = reinterpret_cast<uint32_t&>(h01);
    h.y = reinterpret_cast<uint32_t&>(h23);
}

// ---------------- 0) bprep + zero: fp16 single plane ----------------
__global__ void bprep_kernel(const float* __restrict__ Wb, const float* __restrict__ lA) {
    int idx = blockIdx.x * 256 + threadIdx.x;
    if (idx < Bz * Dz) g_pooled[idx] = 0.f;
    if (idx < NROWS * NCOLS) g_acc[idx] = 0.f;
    if (idx >= NCOLS * (INz / 8)) return;
    int row = idx / (INz / 8);
    int c   = idx % (INz / 8);
    const float* src = (row < OUTz ? Wb + (size_t)row * INz
                                   : lA + (size_t)(row - OUTz) * INz) + c * 8;
    float4 f0 = *(const float4*)src;
    float4 f1 = *(const float4*)(src + 4);
    uint2 h0, h1;
    cvt16(f0, h0);
    cvt16(f1, h1);
    ((uint4*)g_Bf)[idx] = make_uint4(h0.x, h0.y, h1.x, h1.y);
}

// ---------------- 1) fused gemm (fp16 single-term, depth-2 A prefetch) ------
// grid (11, 64), 256 thr, warps (2M x 4N), 2 CTA/SM
__global__ __launch_bounds__(256, 2)
void gemm_mma_kernel(const float* __restrict__ x) {
    extern __shared__ char smem[];
    const uint32_t sb = smem_u32(smem);
    const int t = threadIdx.x;
    const int lane = t & 31;
    const int wid = t >> 5;
    const int wm = wid & 1;
    const int wn = wid >> 1;
    const int m0 = blockIdx.x * MT;
    const int k0 = blockIdx.y * KC;
    const int d0 = k0 >> 6;

    // A loader: 2 float4 per thread per stage, TWO stages held in registers
    const float* aptr[2]; uint32_t asts[2]; bool aval[2]; int abid[2];
    #pragma unroll
    for (int j = 0; j < 2; j++) {
        int idx = t + j * 256;
        int arow = idx >> 3, ac4 = idx & 7;
        int gr = m0 + arow;
        aval[j] = gr < NROWS;
        abid[j] = (aval[j] ? gr : 0) / Vz;
        aptr[j] = x + (size_t)(aval[j] ? gr : 0) * INz + k0 + ac4 * 4;
        asts[j] = (uint32_t)(arow * 80 + ac4 * 8);
    }
    // B loader: 5 x 8B cp.async per thread per stage
    const __half* bsrc[5]; uint32_t bsts[5];
    #pragma unroll
    for (int j = 0; j < 5; j++) {
        int idx = t + j * 256;
        int brow = idx >> 3, c8 = idx & 7;
        bsrc[j] = g_Bf + (size_t)brow * INz + k0 + c8 * 4;
        bsts[j] = (uint32_t)(BH_OFF + brow * 80 + c8 * 8);
    }

    const uint32_t a_lane = (uint32_t)((wm * 32 + (lane & 15)) * 80 + (lane >> 4) * 16);
    const int q = (lane >> 3) & 3;
    const uint32_t b_lane4 = (uint32_t)(wn * 3200 + ((q >> 1) * 8 + (lane & 7)) * 80
                                        + (q & 1) * 16 + BH_OFF);
    const uint32_t b_lane2 = (uint32_t)(wn * 3200 + (32 + (lane & 7)) * 80
                                        + ((lane >> 3) & 1) * 16 + BH_OFF);

    float acc[2][5][4];
    #pragma unroll
    for (int mt = 0; mt < 2; mt++)
        #pragma unroll
        for (int nt = 0; nt < 5; nt++)
            #pragma unroll
            for (int i = 0; i < 4; i++) acc[mt][nt][i] = 0.f;

    // prologue: stages 0 and 1 of A in flight; B stage 0 staged
    float4 areg[2][2];   // [stage parity][j]
    #pragma unroll
    for (int j = 0; j < 2; j++) {
        areg[0][j] = aval[j] ? *(const float4*)aptr[j] : make_float4(0.f, 0.f, 0.f, 0.f);
        areg[1][j] = aval[j] ? *(const float4*)(aptr[j] + KT) : make_float4(0.f, 0.f, 0.f, 0.f);
    }
    #pragma unroll
    for (int j = 0; j < 5; j++) CP8(sb + bsts[j], bsrc[j]);
    CP_COMMIT();

    float rsum0 = 0.f, rsum1 = 0.f;

    for (int s = 0; s < NSTEP; s++) {
        const int par = s & 1;
        const uint32_t base = sb + (uint32_t)par * STAGE;
        char* smbase = smem + (size_t)par * STAGE;
        // STS stage-s A (from its register slot), accumulate pooled sums
        #pragma unroll
        for (int j = 0; j < 2; j++) {
            uint2 h; cvt16(areg[par][j], h);
            *(uint2*)(smbase + AH_OFF + asts[j]) = h;
        }
        rsum0 += (areg[par][0].x + areg[par][0].y) + (areg[par][0].z + areg[par][0].w);
        rsum1 += (areg[par][1].x + areg[par][1].y) + (areg[par][1].z + areg[par][1].w);
        if (s & 1) {
            float v0 = rsum0, v1 = rsum1;
            #pragma unroll
            for (int o = 4; o; o >>= 1) {
                v0 += __shfl_down_sync(0xffffffffu, v0, o, 8);
                v1 += __shfl_down_sync(0xffffffffu, v1, o, 8);
            }
            if ((t & 7) == 0) {
                int d = d0 + (s >> 1);
                if (aval[0]) atomicAdd(&g_pooled[abid[0] * Dz + d], v0);
                if (aval[1]) atomicAdd(&g_pooled[abid[1] * Dz + d], v1);
            }
            rsum0 = 0.f; rsum1 = 0.f;
        }
        CP_WAIT0();
        __syncthreads();
        if (s + 1 < NSTEP) {
            const uint32_t nbase = sb + (uint32_t)((s + 1) & 1) * STAGE;
            const int koff = (s + 1) * KT;
            #pragma unroll
            for (int j = 0; j < 5; j++) CP8(nbase + bsts[j], bsrc[j] + koff);
            CP_COMMIT();
        }
        // LDG stage s+2 into the slot just freed by the STS above (2-stage slack)
        if (s + 2 < NSTEP) {
            const int k2 = (s + 2) * KT;
            #pragma unroll
            for (int j = 0; j < 2; j++)
                areg[par][j] = aval[j] ? *(const float4*)(aptr[j] + k2)
                                       : make_float4(0.f, 0.f, 0.f, 0.f);
        }
        #pragma unroll
        for (int kk = 0; kk < 2; kk++) {
            uint32_t ah[2][4];
            LDSM4(ah[0][0], ah[0][1], ah[0][2], ah[0][3], base + AH_OFF + a_lane + kk * 32);
            LDSM4(ah[1][0], ah[1][1], ah[1][2], ah[1][3], base + AH_OFF + a_lane + 1280 + kk * 32);
            uint32_t bh[10];
            {
                const uint32_t ba = base + b_lane4 + kk * 32;
                LDSM4(bh[0], bh[1], bh[2], bh[3], ba);
                LDSM4(bh[4], bh[5], bh[6], bh[7], ba + 16 * 80);
                LDSM2(bh[8], bh[9], base + b_lane2 + kk * 32);
            }
            #pragma unroll
            for (int nt = 0; nt < 5; nt++) {
                MMAH(acc[0][nt], ah[0], bh[nt * 2], bh[nt * 2 + 1]);
                MMAH(acc[1][nt], ah[1], bh[nt * 2], bh[nt * 2 + 1]);
            }
        }
    }

    #pragma unroll
    for (int mt = 0; mt < 2; mt++) {
        const int r0 = m0 + wm * 32 + mt * 16 + (lane >> 2);
        #pragma unroll
        for (int nt = 0; nt < 5; nt++) {
            const int col = wn * 40 + nt * 8 + (lane & 3) * 2;
            if (r0 < NROWS) {
                atomicAdd(&g_acc[r0 * NCOLS + col],     acc[mt][nt][0]);
                atomicAdd(&g_acc[r0 * NCOLS + col + 1], acc[mt][nt][1]);
            }
            if (r0 + 8 < NROWS) {
                atomicAdd(&g_acc[(r0 + 8) * NCOLS + col],     acc[mt][nt][2]);
                atomicAdd(&g_acc[(r0 + 8) * NCOLS + col + 1], acc[mt][nt][3]);
            }
        }
    }
}

// ---------------- 2) router hidden layer ----------------
__global__ void router_h_kernel(const float* __restrict__ W1, const float* __restrict__ b1) {
    __shared__ float sp[Dz];
    const float invVP = 1.0f / (Vz * Pz);
    const int b = blockIdx.x;
    const int chunk = blockIdx.y;
    const int t = threadIdx.x;
    const int warp = t >> 5, lane = t & 31;
    for (int i = t; i < Dz; i += 256) sp[i] = g_pooled[b * Dz + i] * invVP;
    __syncthreads();
    #pragma unroll
    for (int rr = 0; rr < 4; rr++) {
        int r = chunk * 32 + warp * 4 + rr;
        const float* w = W1 + (size_t)r * Dz;
        float acc = 0.f;
        #pragma unroll
        for (int k = 0; k < Dz / 32; k++) acc = fmaf(sp[k * 32 + lane], w[k * 32 + lane], acc);
        #pragma unroll
        for (int o = 16; o; o >>= 1) acc += __shfl_xor_sync(0xffffffffu, acc, o);
        if (lane == 0) g_h[b * Hz + r] = fmaxf(acc + b1[r], 0.f);
    }
}

// ---------------- 3) final: logits + softmax + top-2 + bias + LoRA combine --
__global__ __launch_bounds__(256)
void final_kernel(const float* __restrict__ W2, const float* __restrict__ b2,
                  const float* __restrict__ b_base, const float* __restrict__ lB,
                  float* __restrict__ out, float* __restrict__ out_probs) {
    const int row = blockIdx.x;
    const int t = threadIdx.x;
    const int b = row / Vz;
    const int warp = t >> 5, lane = t & 31;
    __shared__ float sh[Hz];
    __shared__ float sl[Ez];
    __shared__ float sw[Ez];
    __shared__ float temp[Ez * Rz];
    sh[t] = g_h[b * Hz + t];
    float v = 0.f;
    if (t < NCOLS) {
        v = g_acc[row * NCOLS + t];
        if (t >= OUTz) temp[t - OUTz] = v;
    }
    __syncthreads();
    if (warp < Ez) {
        const float* w = W2 + (size_t)warp * Hz;
        float acc = 0.f;
        #pragma unroll
        for (int k = 0; k < Hz / 32; k++) acc = fmaf(sh[k * 32 + lane], w[k * 32 + lane], acc);
        #pragma unroll
        for (int o = 16; o; o >>= 1) acc += __shfl_xor_sync(0xffffffffu, acc, o);
        if (lane == 0) sl[warp] = acc + b2[warp];
    }
    __syncthreads();
    if (t == 0) {
        float mx = -1e30f;
        #pragma unroll
        for (int e = 0; e < Ez; e++) mx = fmaxf(mx, sl[e]);
        float pr[Ez]; float se = 0.f;
        #pragma unroll
        for (int e = 0; e < Ez; e++) { pr[e] = expf(sl[e] - mx); se += pr[e]; }
        float inv = 1.0f / se;
        #pragma unroll
        for (int e = 0; e < Ez; e++) pr[e] *= inv;
        if (row % Vz == 0) {
            #pragma unroll
            for (int e = 0; e < Ez; e++) out_probs[b * Ez + e] = pr[e];
        }
        int i0 = 0;
        #pragma unroll
        for (int e = 1; e < Ez; e++) if (pr[e] > pr[i0]) i0 = e;
        int i1 = (i0 == 0) ? 1 : 0;
        #pragma unroll
        for (int e = 0; e < Ez; e++) if (e != i0 && pr[e] > pr[i1]) i1 = e;
        float s2 = pr[i0] + pr[i1];
        if (s2 < 1e-6f) s2 = 1e-6f;
        float inv2 = SCALE / s2;
        #pragma unroll
        for (int e = 0; e < Ez; e++) sw[e] = 0.f;
        sw[i0] = pr[i0] * inv2;
        sw[i1] = pr[i1] * inv2;
    }
    __syncthreads();
    if (t < OUTz) {
        float o = b_base[t] + v;
        #pragma unroll
        for (int e = 0; e < Ez; e++) {
            float w = sw[e];
            if (w != 0.f) {
                float d = 0.f;
                #pragma unroll
                for (int r = 0; r < Rz; r++)
                    d = fmaf(lB[((size_t)e * OUTz + t) * Rz + r], temp[e * Rz + r], d);
                o = fmaf(w, d, o);
            }
        }
        out[(size_t)row * OUTz + t] = o;
    }
}

// ---------------- launch ----------------
extern "C" void kernel_launch(void* const* d_in, const int* in_sizes, int n_in,
                              void* d_out, int out_size) {
    const float* x   = (const float*)d_in[0];
    const float* Wb  = (const float*)d_in[1];
    const float* bb  = (const float*)d_in[2];
    const float* W1  = (const float*)d_in[3];
    const float* b1v = (const float*)d_in[4];
    const float* W2  = (const float*)d_in[5];
    const float* b2v = (const float*)d_in[6];
    const float* lA  = (const float*)d_in[7];
    const float* lB  = (const float*)d_in[8];
    float* out = (float*)d_out;
    float* out_probs = out + (size_t)NROWS * OUTz;

    cudaFuncSetAttribute(gemm_mma_kernel, cudaFuncAttributeMaxDynamicSharedMemorySize, SM_TOTAL);

    bprep_kernel<<<(NCOLS * (INz / 8) + 255) / 256, 256>>>(Wb, lA);
    gemm_mma_kernel<<<dim3(11, SPLITK), 256, SM_TOTAL>>>(x);
    router_h_kernel<<<dim3(Bz, Hz / 32), 256>>>(W1, b1v);
    final_kernel<<<NROWS, 256>>>(W2, b2v, bb, lB, out, out_probs);
    (void)in_sizes; (void)n_in; (void)out_size;
}

// round 16
// speedup vs baseline: 1.3456x; 1.3456x over previous
#include <cuda_runtime.h>
#include <cuda_fp16.h>
#include <cstdint>

#define Bz 32
#define Vz 21
#define Dz 512
#define Pz 64
#define INz 32768
#define OUTz 96
#define Ez 8
#define Rz 8
#define Hz 256
#define NROWS (Bz*Vz)          /* 672 */
#define NCOLS (OUTz + Ez*Rz)   /* 160 */
#define SPLITK 64
#define KC (INz/SPLITK)        /* 512 */
#define SCALE 2.0f

// GEMM tiling
#define MT 64
#define KT 32
#define NSTEP (KC/KT)          /* 16 */
#define AH_OFF 0
#define BH_OFF 5120            /* 64*80 */
#define STAGE  17920           /* 5120 + 160*80 */
#define SM_TOTAL (2*STAGE)     /* 35840 */

// ---------------- device scratch ----------------
__device__ float g_pooled[Bz*Dz];
__device__ float g_h[Bz*Hz];
__device__ float g_acc[NROWS*NCOLS];
__device__ __half g_Bf[(size_t)NCOLS*INz];   // B-matrix, single fp16 plane

// ---------------- PTX helpers ----------------
__device__ __forceinline__ uint32_t smem_u32(const void* p) {
    uint32_t a;
    asm("{ .reg .u64 t; cvta.to.shared.u64 t, %1; cvt.u32.u64 %0, t; }" : "=r"(a) : "l"(p));
    return a;
}
#define CP8(dst, src)   asm volatile("cp.async.ca.shared.global [%0], [%1], 8;" :: "r"(dst), "l"(src) : "memory")
#define CP_COMMIT()     asm volatile("cp.async.commit_group;" ::: "memory")
#define CP_WAIT0()      asm volatile("cp.async.wait_group 0;" ::: "memory")
#define LDSM4(r0,r1,r2,r3,addr) \
    asm volatile("ldmatrix.sync.aligned.m8n8.x4.shared.b16 {%0,%1,%2,%3}, [%4];" \
        : "=r"(r0),"=r"(r1),"=r"(r2),"=r"(r3) : "r"(addr))
#define LDSM2(r0,r1,addr) \
    asm volatile("ldmatrix.sync.aligned.m8n8.x2.shared.b16 {%0,%1}, [%2];" \
        : "=r"(r0),"=r"(r1) : "r"(addr))
#define MMAH(d, a, b0, b1) \
    asm volatile("mma.sync.aligned.m16n8k16.row.col.f32.f16.f16.f32 " \
        "{%0,%1,%2,%3},{%4,%5,%6,%7},{%8,%9},{%0,%1,%2,%3};" \
        : "+f"((d)[0]),"+f"((d)[1]),"+f"((d)[2]),"+f"((d)[3]) \
        : "r"((a)[0]),"r"((a)[1]),"r"((a)[2]),"r"((a)[3]), "r"(b0),"r"(b1))

__device__ __forceinline__ void cvt16(float4 f, uint2& h) {
    __half2 h01 = __floats2half2_rn(f.x, f.y);
    __half2 h23 = __floats2half2_rn(f.z, f.w);
    h.x = reinterpret_cast<uint32_t&>(h01);
    h.y = reinterpret_cast<uint32_t&>(h23);
}

// ---------------- 0) bprep + zero: fp16 single plane ----------------
__global__ void bprep_kernel(const float* __restrict__ Wb, const float* __restrict__ lA) {
    int idx = blockIdx.x * 256 + threadIdx.x;
    if (idx < Bz * Dz) g_pooled[idx] = 0.f;
    if (idx < NROWS * NCOLS) g_acc[idx] = 0.f;
    if (idx >= NCOLS * (INz / 8)) return;
    int row = idx / (INz / 8);
    int c   = idx % (INz / 8);
    const float* src = (row < OUTz ? Wb + (size_t)row * INz
                                   : lA + (size_t)(row - OUTz) * INz) + c * 8;
    float4 f0 = *(const float4*)src;
    float4 f1 = *(const float4*)(src + 4);
    uint2 h0, h1;
    cvt16(f0, h0);
    cvt16(f1, h1);
    ((uint4*)g_Bf)[idx] = make_uint4(h0.x, h0.y, h1.x, h1.y);
}

// ---------------- 1) fused gemm (fp16 single-term; R14 structure + LDG hoist)
// grid (11, 64), 256 thr, warps (2M x 4N), 2 CTA/SM
__global__ __launch_bounds__(256, 2)
void gemm_mma_kernel(const float* __restrict__ x) {
    extern __shared__ char smem[];
    const uint32_t sb = smem_u32(smem);
    const int t = threadIdx.x;
    const int lane = t & 31;
    const int wid = t >> 5;
    const int wm = wid & 1;
    const int wn = wid >> 1;
    const int m0 = blockIdx.x * MT;
    const int k0 = blockIdx.y * KC;
    const int d0 = k0 >> 6;

    // A loader: 2 float4 per thread per stage
    const float* aptr[2]; uint32_t asts[2]; bool aval[2]; int abid[2];
    #pragma unroll
    for (int j = 0; j < 2; j++) {
        int idx = t + j * 256;
        int arow = idx >> 3, ac4 = idx & 7;
        int gr = m0 + arow;
        aval[j] = gr < NROWS;
        abid[j] = (aval[j] ? gr : 0) / Vz;
        aptr[j] = x + (size_t)(aval[j] ? gr : 0) * INz + k0 + ac4 * 4;
        asts[j] = (uint32_t)(arow * 80 + ac4 * 8);
    }
    // B loader: 5 x 8B cp.async per thread per stage
    const __half* bsrc[5]; uint32_t bsts[5];
    #pragma unroll
    for (int j = 0; j < 5; j++) {
        int idx = t + j * 256;
        int brow = idx >> 3, c8 = idx & 7;
        bsrc[j] = g_Bf + (size_t)brow * INz + k0 + c8 * 4;
        bsts[j] = (uint32_t)(BH_OFF + brow * 80 + c8 * 8);
    }

    const uint32_t a_lane = (uint32_t)((wm * 32 + (lane & 15)) * 80 + (lane >> 4) * 16);
    const int q = (lane >> 3) & 3;
    const uint32_t b_lane4 = (uint32_t)(wn * 3200 + ((q >> 1) * 8 + (lane & 7)) * 80
                                        + (q & 1) * 16 + BH_OFF);
    const uint32_t b_lane2 = (uint32_t)(wn * 3200 + (32 + (lane & 7)) * 80
                                        + ((lane >> 3) & 1) * 16 + BH_OFF);

    float acc[2][5][4];
    #pragma unroll
    for (int mt = 0; mt < 2; mt++)
        #pragma unroll
        for (int nt = 0; nt < 5; nt++)
            #pragma unroll
            for (int i = 0; i < 4; i++) acc[mt][nt][i] = 0.f;

    float4 areg[2];
    #pragma unroll
    for (int j = 0; j < 2; j++)
        areg[j] = aval[j] ? *(const float4*)aptr[j] : make_float4(0.f, 0.f, 0.f, 0.f);
    #pragma unroll
    for (int j = 0; j < 5; j++) CP8(sb + bsts[j], bsrc[j]);
    CP_COMMIT();

    float rsum0 = 0.f, rsum1 = 0.f;

    for (int s = 0; s < NSTEP; s++) {
        const uint32_t base = sb + (uint32_t)(s & 1) * STAGE;
        char* smbase = smem + (size_t)(s & 1) * STAGE;
        // STS stage-s A, accumulate pooled sums (consumes areg)
        #pragma unroll
        for (int j = 0; j < 2; j++) {
            uint2 h; cvt16(areg[j], h);
            *(uint2*)(smbase + AH_OFF + asts[j]) = h;
        }
        rsum0 += (areg[0].x + areg[0].y) + (areg[0].z + areg[0].w);
        rsum1 += (areg[1].x + areg[1].y) + (areg[1].z + areg[1].w);
        // hoisted: LDG A(s+1) into the now-free areg slot, BEFORE the barrier
        if (s + 1 < NSTEP) {
            const int koff = (s + 1) * KT;
            #pragma unroll
            for (int j = 0; j < 2; j++)
                areg[j] = aval[j] ? *(const float4*)(aptr[j] + koff)
                                  : make_float4(0.f, 0.f, 0.f, 0.f);
        }
        if (s & 1) {
            float v0 = rsum0, v1 = rsum1;
            #pragma unroll
            for (int o = 4; o; o >>= 1) {
                v0 += __shfl_down_sync(0xffffffffu, v0, o, 8);
                v1 += __shfl_down_sync(0xffffffffu, v1, o, 8);
            }
            if ((t & 7) == 0) {
                int d = d0 + (s >> 1);
                if (aval[0]) atomicAdd(&g_pooled[abid[0] * Dz + d], v0);
                if (aval[1]) atomicAdd(&g_pooled[abid[1] * Dz + d], v1);
            }
            rsum0 = 0.f; rsum1 = 0.f;
        }
        CP_WAIT0();
        __syncthreads();
        if (s + 1 < NSTEP) {
            const uint32_t nbase = sb + (uint32_t)((s + 1) & 1) * STAGE;
            const int koff = (s + 1) * KT;
            #pragma unroll
            for (int j = 0; j < 5; j++) CP8(nbase + bsts[j], bsrc[j] + koff);
            CP_COMMIT();
        }
        #pragma unroll
        for (int kk = 0; kk < 2; kk++) {
            uint32_t ah[2][4];
            LDSM4(ah[0][0], ah[0][1], ah[0][2], ah[0][3], base + AH_OFF + a_lane + kk * 32);
            LDSM4(ah[1][0], ah[1][1], ah[1][2], ah[1][3], base + AH_OFF + a_lane + 1280 + kk * 32);
            uint32_t bh[10];
            {
                const uint32_t ba = base + b_lane4 + kk * 32;
                LDSM4(bh[0], bh[1], bh[2], bh[3], ba);
                LDSM4(bh[4], bh[5], bh[6], bh[7], ba + 16 * 80);
                LDSM2(bh[8], bh[9], base + b_lane2 + kk * 32);
            }
            #pragma unroll
            for (int nt = 0; nt < 5; nt++) {
                MMAH(acc[0][nt], ah[0], bh[nt * 2], bh[nt * 2 + 1]);
                MMAH(acc[1][nt], ah[1], bh[nt * 2], bh[nt * 2 + 1]);
            }
        }
    }

    #pragma unroll
    for (int mt = 0; mt < 2; mt++) {
        const int r0 = m0 + wm * 32 + mt * 16 + (lane >> 2);
        #pragma unroll
        for (int nt = 0; nt < 5; nt++) {
            const int col = wn * 40 + nt * 8 + (lane & 3) * 2;
            if (r0 < NROWS) {
                atomicAdd(&g_acc[r0 * NCOLS + col],     acc[mt][nt][0]);
                atomicAdd(&g_acc[r0 * NCOLS + col + 1], acc[mt][nt][1]);
            }
            if (r0 + 8 < NROWS) {
                atomicAdd(&g_acc[(r0 + 8) * NCOLS + col],     acc[mt][nt][2]);
                atomicAdd(&g_acc[(r0 + 8) * NCOLS + col + 1], acc[mt][nt][3]);
            }
        }
    }
}

// ---------------- 2) router hidden layer ----------------
__global__ void router_h_kernel(const float* __restrict__ W1, const float* __restrict__ b1) {
    __shared__ float sp[Dz];
    const float invVP = 1.0f / (Vz * Pz);
    const int b = blockIdx.x;
    const int chunk = blockIdx.y;
    const int t = threadIdx.x;
    const int warp = t >> 5, lane = t & 31;
    for (int i = t; i < Dz; i += 256) sp[i] = g_pooled[b * Dz + i] * invVP;
    __syncthreads();
    #pragma unroll
    for (int rr = 0; rr < 4; rr++) {
        int r = chunk * 32 + warp * 4 + rr;
        const float* w = W1 + (size_t)r * Dz;
        float acc = 0.f;
        #pragma unroll
        for (int k = 0; k < Dz / 32; k++) acc = fmaf(sp[k * 32 + lane], w[k * 32 + lane], acc);
        #pragma unroll
        for (int o = 16; o; o >>= 1) acc += __shfl_xor_sync(0xffffffffu, acc, o);
        if (lane == 0) g_h[b * Hz + r] = fmaxf(acc + b1[r], 0.f);
    }
}

// ---------------- 3) final: logits + softmax + top-2 + bias + LoRA combine --
__global__ __launch_bounds__(256)
void final_kernel(const float* __restrict__ W2, const float* __restrict__ b2,
                  const float* __restrict__ b_base, const float* __restrict__ lB,
                  float* __restrict__ out, float* __restrict__ out_probs) {
    const int row = blockIdx.x;
    const int t = threadIdx.x;
    const int b = row / Vz;
    const int warp = t >> 5, lane = t & 31;
    __shared__ float sh[Hz];
    __shared__ float sl[Ez];
    __shared__ float sw[Ez];
    __shared__ float temp[Ez * Rz];
    sh[t] = g_h[b * Hz + t];
    float v = 0.f;
    if (t < NCOLS) {
        v = g_acc[row * NCOLS + t];
        if (t >= OUTz) temp[t - OUTz] = v;
    }
    __syncthreads();
    if (warp < Ez) {
        const float* w = W2 + (size_t)warp * Hz;
        float acc = 0.f;
        #pragma unroll
        for (int k = 0; k < Hz / 32; k++) acc = fmaf(sh[k * 32 + lane], w[k * 32 + lane], acc);
        #pragma unroll
        for (int o = 16; o; o >>= 1) acc += __shfl_xor_sync(0xffffffffu, acc, o);
        if (lane == 0) sl[warp] = acc + b2[warp];
    }
    __syncthreads();
    if (t == 0) {
        float mx = -1e30f;
        #pragma unroll
        for (int e = 0; e < Ez; e++) mx = fmaxf(mx, sl[e]);
        float pr[Ez]; float se = 0.f;
        #pragma unroll
        for (int e = 0; e < Ez; e++) { pr[e] = expf(sl[e] - mx); se += pr[e]; }
        float inv = 1.0f / se;
        #pragma unroll
        for (int e = 0; e < Ez; e++) pr[e] *= inv;
        if (row % Vz == 0) {
            #pragma unroll
            for (int e = 0; e < Ez; e++) out_probs[b * Ez + e] = pr[e];
        }
        int i0 = 0;
        #pragma unroll
        for (int e = 1; e < Ez; e++) if (pr[e] > pr[i0]) i0 = e;
        int i1 = (i0 == 0) ? 1 : 0;
        #pragma unroll
        for (int e = 0; e < Ez; e++) if (e != i0 && pr[e] > pr[i1]) i1 = e;
        float s2 = pr[i0] + pr[i1];
        if (s2 < 1e-6f) s2 = 1e-6f;
        float inv2 = SCALE / s2;
        #pragma unroll
        for (int e = 0; e < Ez; e++) sw[e] = 0.f;
        sw[i0] = pr[i0] * inv2;
        sw[i1] = pr[i1] * inv2;
    }
    __syncthreads();
    if (t < OUTz) {
        float o = b_base[t] + v;
        #pragma unroll
        for (int e = 0; e < Ez; e++) {
            float w = sw[e];
            if (w != 0.f) {
                float d = 0.f;
                #pragma unroll
                for (int r = 0; r < Rz; r++)
                    d = fmaf(lB[((size_t)e * OUTz + t) * Rz + r], temp[e * Rz + r], d);
                o = fmaf(w, d, o);
            }
        }
        out[(size_t)row * OUTz + t] = o;
    }
}

// ---------------- launch ----------------
extern "C" void kernel_launch(void* const* d_in, const int* in_sizes, int n_in,
                              void* d_out, int out_size) {
    const float* x   = (const float*)d_in[0];
    const float* Wb  = (const float*)d_in[1];
    const float* bb  = (const float*)d_in[2];
    const float* W1  = (const float*)d_in[3];
    const float* b1v = (const float*)d_in[4];
    const float* W2  = (const float*)d_in[5];
    const float* b2v = (const float*)d_in[6];
    const float* lA  = (const float*)d_in[7];
    const float* lB  = (const float*)d_in[8];
    float* out = (float*)d_out;
    float* out_probs = out + (size_t)NROWS * OUTz;

    cudaFuncSetAttribute(gemm_mma_kernel, cudaFuncAttributeMaxDynamicSharedMemorySize, SM_TOTAL);

    bprep_kernel<<<(NCOLS * (INz / 8) + 255) / 256, 256>>>(Wb, lA);
    gemm_mma_kernel<<<dim3(11, SPLITK), 256, SM_TOTAL>>>(x);
    router_h_kernel<<<dim3(Bz, Hz / 32), 256>>>(W1, b1v);
    final_kernel<<<NROWS, 256>>>(W2, b2v, bb, lB, out, out_probs);
    (void)in_sizes; (void)n_in; (void)out_size;
}